// round 16
// baseline (speedup 1.0000x reference)
#include <cuda_runtime.h>
#include <math.h>

#define KK 769
#define MM 384
#define BB 64
#define LL 256
#define AA 21
#define ESTR 772
#define NEGV (-1.0e32f)

__device__ __align__(16) float g_eobs[(AA + 1) * ESTR];
__device__ float g_cm[KK];
__device__ float g_ci[KK];
__device__ float g_cf[KK];
__device__ float g_et[KK];
__device__ float g_w[MM];
__device__ float g_einit[KK];

// ---------------- fused prep: CTA0 = transition constants, CTA1-2 = emission table ----------------
__global__ __launch_bounds__(512) void prep_fused(
    const float* __restrict__ pre,  const float* __restrict__ iseq,
    const float* __restrict__ ins,  const float* __restrict__ del)
{
    const int tid = threadIdx.x, lane = tid & 31, wid = tid >> 5;

    if (blockIdx.x > 0) {
        // ---------- emission table: one state per thread ----------
        const int k = (blockIdx.x - 1) * 512 + tid;
        if (k >= KK) return;
        const float* row = (k < MM) ? (pre + k * AA) : (iseq + (k - MM) * AA);
        float mx = -INFINITY;
        #pragma unroll
        for (int a = 0; a < AA; a++) mx = fmaxf(mx, row[a]);
        float sm = 0.f;
        #pragma unroll
        for (int a = 0; a < AA; a++) sm += __expf(row[a] - mx);
        float l = mx + __logf(sm);
        float sm2 = 0.f;
        #pragma unroll
        for (int a = 0; a < AA; a++) sm2 += __expf(row[a] - l);
        float nrm = l + __logf(sm2);
        #pragma unroll
        for (int a = 0; a < AA; a++) g_eobs[a * ESTR + k] = __expf(row[a] - nrm);
        g_eobs[AA * ESTR + k] = 1.0f;
        return;
    }

    // ---------- CTA 0: transition constants + init ----------
    __shared__ float lre[(MM + 1) * 6], lue[(MM + 1) * 6];
    __shared__ float sC[MM + 2], sW2[MM + 1], sQt[MM + 1], sG[MM + 1];
    __shared__ float WT[16], ST[16], FIN[16], red[16];
    __shared__ float sInit[KK];

    for (int idx = tid; idx < MM * 3; idx += 512) {
        float x0 = ins[idx * 2], x1 = ins[idx * 2 + 1];
        float mx = fmaxf(x0, x1);
        float l = mx + __logf(__expf(x0 - mx) + __expf(x1 - mx));
        lre[idx * 2] = x0 - l; lre[idx * 2 + 1] = x1 - l;
        x0 = del[idx * 2]; x1 = del[idx * 2 + 1];
        mx = fmaxf(x0, x1);
        l = mx + __logf(__expf(x0 - mx) + __expf(x1 - mx));
        lue[idx * 2] = x0 - l; lue[idx * 2 + 1] = x1 - l;
    }
    if (tid < 3) {
        lre[(MM * 3 + tid) * 2 + 0] = NEGV; lre[(MM * 3 + tid) * 2 + 1] = 0.f;
        lue[(MM * 3 + tid) * 2 + 0] = 0.f;  lue[(MM * 3 + tid) * 2 + 1] = NEGV;
    }
    __syncthreads();

    { // C (exclusive cumsum of d2), w2, Qt
        float d2 = 0.f;
        if (tid < MM) d2 = lre[(tid * 3 + 2) * 2 + 0] + lue[(tid * 3 + 2) * 2 + 1];
        float inc = d2;
        #pragma unroll
        for (int o = 1; o < 32; o <<= 1) {
            float t = __shfl_up_sync(0xffffffffu, inc, o);
            if (lane >= o) inc += t;
        }
        if (lane == 31) WT[wid] = inc;
        __syncthreads();
        float off = 0.f;
        for (int j = 0; j < wid; j++) off += WT[j];
        if (tid < MM) { sC[tid + 1] = inc + off; sW2[tid] = __expf(d2); }
        if (tid == 0) { sC[0] = 0.f; sC[MM + 1] = 0.f; sW2[MM] = 0.f; }
        if (tid <= MM) {
            float q = __expf(lre[(tid * 3 + 2) * 2 + 1]);
            if (tid < MM) q += __expf(lre[(tid * 3 + 2) * 2 + 0] + lue[(tid * 3 + 2) * 2 + 0]);
            sQt[tid] = q;
        }
        __syncthreads();
    }
    { // G via reverse affine scan
        float A = 1.f, Bv = 0.f;
        if (tid < MM) { A = sW2[MM - tid]; Bv = sQt[MM - tid]; }
        #pragma unroll
        for (int o = 1; o < 32; o <<= 1) {
            float Wp = __shfl_up_sync(0xffffffffu, A, o);
            float Sp = __shfl_up_sync(0xffffffffu, Bv, o);
            if (lane >= o) { Bv = fmaf(A, Sp, Bv); A *= Wp; }
        }
        if (lane == 31 && wid < 12) { WT[wid] = A; ST[wid] = Bv; }
        __syncthreads();
        if (wid == 0) {
            float Wt = (lane < 12) ? WT[lane] : 1.f;
            float St = (lane < 12) ? ST[lane] : 0.f;
            #pragma unroll
            for (int o = 1; o < 16; o <<= 1) {
                float Wp = __shfl_up_sync(0xffffffffu, Wt, o);
                float Sp = __shfl_up_sync(0xffffffffu, St, o);
                if (lane >= o) { St = fmaf(Wt, Sp, St); Wt *= Wp; }
            }
            float e = __shfl_up_sync(0xffffffffu, St, 1);
            if (lane == 0) e = 0.f;
            if (lane < 12) FIN[lane] = e;
        }
        __syncthreads();
        if (tid < MM) sG[MM - 1 - tid] = fmaf(A, FIN[wid], Bv);
        if (tid == 0) sG[MM] = 0.f;
        __syncthreads();
    }
    for (int k = tid; k < KK; k += 512) {
        const int m = (k < MM) ? k : k - MM;
        const int g = (k < MM) ? 0 : 1;
        const int s = m + 1 - g;
        float src_stay  = lre[(s * 3 + g) * 2 + 0];
        float src_ins   = lre[(s * 3 + g) * 2 + 1];
        float src_match = lue[(s * 3 + g) * 2 + 0];
        float src_del   = lue[(s * 3 + g) * 2 + 1];
        float dmatch = src_stay + src_match, dins = src_ins, cflog = src_stay + src_del;
        float rowsum = __expf(dins) + ((s < MM) ? __expf(dmatch) : 0.f) + __expf(cflog) * sG[s];
        float lse = __logf(rowsum);
        g_cm[k] = __expf(dmatch - lse);
        g_ci[k] = __expf(dins - lse);
        g_cf[k] = __expf(cflog - lse);
        float tterm = (g == 1) ? lre[(m * 3 + 2) * 2 + 1]
                               : (lre[(m * 3 + 2) * 2 + 0] + lue[(m * 3 + 2) * 2 + 0]);
        g_et[k] = __expf(tterm);
        float initv;
        if (m == 0) initv = (g == 1) ? lre[1] : (lre[0] + lue[0]);
        else        initv = lre[0] + lue[1] - sC[1] + sC[m] + tterm;
        sInit[k] = initv;
    }
    if (tid < MM) g_w[tid] = sW2[tid];
    __syncthreads();
    { // normalized exp(init)
        float mloc = -INFINITY;
        for (int k = tid; k < KK; k += 512) mloc = fmaxf(mloc, sInit[k]);
        #pragma unroll
        for (int o = 16; o; o >>= 1) mloc = fmaxf(mloc, __shfl_xor_sync(0xffffffffu, mloc, o));
        if (lane == 0) red[wid] = mloc;
        __syncthreads();
        float mxI = red[0];
        #pragma unroll
        for (int j = 1; j < 16; j++) mxI = fmaxf(mxI, red[j]);
        __syncthreads();
        float s0 = 0.f;
        for (int k = tid; k < KK; k += 512) s0 += __expf(sInit[k] - mxI);
        #pragma unroll
        for (int o = 16; o; o >>= 1) s0 += __shfl_xor_sync(0xffffffffu, s0, o);
        if (lane == 0) red[wid] = s0;
        __syncthreads();
        float Z = 0.f;
        for (int j = 0; j < 16; j++) Z += red[j];
        float lz = mxI + __logf(Z);
        for (int k = tid; k < KK; k += 512) g_einit[k] = __expf(sInit[k] - lz);
    }
}

// ---------------- one forward step: constant-W scan (NLEV levels), ONE barrier ----------------
template <bool RESC, int P, int NLEV>
__device__ __forceinline__ void stepfn(
    const float (&um)[3], const float (&ui)[3], float uxin,
    float (&vm)[3], float (&vi)[3], float& vx,
    const float (&w_)[3], const float (&cfa)[3], const float (&cfb)[3],
    const float (&cma)[3], const float (&cmb)[3],
    const float (&cia)[3], const float (&cib)[3],
    const float (&etm)[3], const float (&eti)[3],
    const float (&WL)[5], float Wexcl, float WT1, float WT2,
    float kw1, float kw2, float kw3,
    float2 (*s_T)[4], float4* s_bnd,
    int j0, int lane, int wid, bool l127,
    float et_x, float ci_xa, float ci_xb,
    const float* __restrict__ ob, int& pacc)
{
    float em[3], ei[3];
    #pragma unroll
    for (int q = 0; q < 3; q++) { em[q] = ob[j0 + q]; ei[q] = ob[MM + j0 + q]; }
    float e_x = l127 ? ob[KK - 1] : 0.f;

    float ubm1 = __shfl_up_sync(0xffffffffu, um[2], 1);
    float ub_s = lane ? ubm1 : 0.f;

    float Sr[3];
    Sr[0] = fmaf(ub_s, cfb[0], ui[0] * cfa[0]);
    Sr[1] = fmaf(um[0], cfb[1], ui[1] * cfa[1]);
    Sr[2] = fmaf(um[1], cfb[2], ui[2] * cfa[2]);
    float Sv = Sr[0];
    Sv = fmaf(w_[1], Sv, Sr[1]);
    Sv = fmaf(w_[2], Sv, Sr[2]);

    // S-only inclusive affine scan; levels >= NLEV have WL == 0 (verified at init)
    #pragma unroll
    for (int k = 0; k < NLEV; k++) {
        const int o = 1 << k;
        float Sp = __shfl_up_sync(0xffffffffu, Sv, o);
        if (lane >= o) Sv = fmaf(WL[k], Sp, Sv);
    }

    float zs = 0.f;
    if (RESC) {
        zs = ((um[0] + um[1]) + (um[2] + uxin)) + ((ui[0] + ui[1]) + ui[2]);
        #pragma unroll
        for (int o = 16; o; o >>= 1) zs += __shfl_xor_sync(0xffffffffu, zs, o);
    }
    float Sp1 = __shfl_up_sync(0xffffffffu, Sv, 1);   // pre-barrier
    if (lane == 31) s_T[P][wid] = make_float2(Sv, zs);
    __syncthreads();

    float2 T0 = s_T[P][0], T1 = s_T[P][1], T2 = s_T[P][2];
    float rz = 1.f;
    if (RESC) {
        float2 T3 = s_T[P][3];
        float Tz = (T0.y + T1.y) + (T2.y + T3.y);
        unsigned ze = (__float_as_uint(Tz) >> 23) & 255u;
        pacc += (int)ze - 127;
        rz = __uint_as_float((254u - ze) << 23);
    }
    float4 bv = s_bnd[P];
    float bc1 = bv.y * kw1, bc2 = bv.z * kw2, bc3 = bv.w * kw3;
    float Fin;
    if (NLEV == 2) {
        // WT1 == WT2 == 0 exactly in the truncated regime
        Fin = (wid == 0) ? 0.f
            : (wid == 1) ? (T0.x + bc1)
            : (wid == 2) ? (T1.x + bc2)
                         : (T2.x + bc3);
    } else {
        Fin = 0.f;
        if (wid > 0) Fin = T0.x + bc1;
        if (wid > 1) Fin = fmaf(WT1, Fin, T1.x) + bc2;
        if (wid > 2) Fin = fmaf(WT2, Fin, T2.x) + bc3;
    }

    float Fexp = lane ? fmaf(Wexcl, Fin, Sp1) : Fin;
    float bc_own = (wid == 1) ? bc1 : ((wid == 2) ? bc2 : ((wid == 3) ? bc3 : 0.f));
    float ubw    = (wid == 1) ? bv.y : ((wid == 2) ? bv.z : ((wid == 3) ? bv.w : 0.f));
    float F0  = lane ? Fexp : (Fexp - bc_own);
    float ub0 = lane ? ubm1 : ubw;

    float prm = fmaf(ub0, cmb[0], fmaf(ui[0], cma[0], etm[0] * F0));
    float pri = fmaf(ub0, cib[0], fmaf(ui[0], cia[0], eti[0] * F0));
    vm[0] = RESC ? prm * em[0] * rz : prm * em[0];
    vi[0] = RESC ? pri * ei[0] * rz : pri * ei[0];
    float F = fmaf(w_[0], Fexp, Sr[0]);
    prm = fmaf(um[0], cmb[1], fmaf(ui[1], cma[1], etm[1] * F));
    pri = fmaf(um[0], cib[1], fmaf(ui[1], cia[1], eti[1] * F));
    vm[1] = RESC ? prm * em[1] * rz : prm * em[1];
    vi[1] = RESC ? pri * ei[1] * rz : pri * ei[1];
    F = fmaf(w_[1], F, Sr[1]);
    prm = fmaf(um[1], cmb[2], fmaf(ui[2], cma[2], etm[2] * F));
    pri = fmaf(um[1], cib[2], fmaf(ui[2], cia[2], eti[2] * F));
    vm[2] = RESC ? prm * em[2] * rz : prm * em[2];
    vi[2] = RESC ? pri * ei[2] * rz : pri * ei[2];
    vx = 0.f;
    if (l127) {
        F = fmaf(w_[2], F, Sr[2]);
        float prx = fmaf(et_x, F, fmaf(um[2], ci_xb, uxin * ci_xa));
        vx = RESC ? prx * e_x * rz : prx * e_x;
    }
    if (lane == 31 && wid < 3)
        ((float*)&s_bnd[P ^ 1])[wid + 1] = vm[2];
}

// ---------------- forward recursion: 4 warps, alpha in registers, 1 bar/step ----------------
__global__ void __launch_bounds__(128) hmm_forward(const float* __restrict__ seq,
                                                   const float* __restrict__ lscale,
                                                   float* __restrict__ out)
{
    __shared__ float2 s_T[2][4];
    __shared__ float4 s_bnd[2];
    __shared__ float  s_red[4];
    __shared__ int    s_let[LL];

    const int b = blockIdx.x, tid = threadIdx.x, lane = tid & 31, wid = tid >> 5;
    const int j0 = tid * 3;
    const bool l127 = (tid == 127);

    for (int l = tid; l < LL; l += 128) {
        const float* row = seq + ((size_t)b * LL + l) * AA;
        int let = AA;
        #pragma unroll
        for (int a = 0; a < AA; a++)
            if (row[a] > 0.5f) let = a;
        s_let[l] = let * ESTR;
    }

    float w_[3], cfa[3], cfb[3], cma[3], cmb[3], cia[3], cib[3], etm[3], eti[3];
    #pragma unroll
    for (int q = 0; q < 3; q++) {
        const int j = j0 + q;
        w_[q]  = g_w[j];
        cfa[q] = g_cf[MM + j];  cfb[q] = j ? g_cf[j - 1] : 0.f;
        cma[q] = g_cm[MM + j];  cmb[q] = j ? g_cm[j - 1] : 0.f;
        cia[q] = g_ci[MM + j];  cib[q] = j ? g_ci[j - 1] : 0.f;
        etm[q] = g_et[j];       eti[q] = g_et[MM + j];
    }
    const float kw1 = __fdividef(g_cf[95],  g_w[96]);
    const float kw2 = __fdividef(g_cf[191], g_w[192]);
    const float kw3 = __fdividef(g_cf[287], g_w[288]);
    float et_x = 0.f, ci_xa = 0.f, ci_xb = 0.f;
    if (l127) { et_x = g_et[KK - 1]; ci_xa = g_ci[KK - 1]; ci_xb = g_ci[MM - 1]; }

    // constant-W scan multipliers (one dummy W-only scan)
    float WL[5], Wfin;
    {
        float Wv = w_[0] * w_[1] * w_[2];
        #pragma unroll
        for (int k = 0; k < 5; k++) {
            const int o = 1 << k;
            WL[k] = Wv;
            float Wp = __shfl_up_sync(0xffffffffu, Wv, o);
            if (lane >= o) Wv *= Wp;
        }
        Wfin = Wv;
    }
    const float Wexcl = __shfl_up_sync(0xffffffffu, Wfin, 1);
    if (lane == 31) s_red[wid] = Wfin;

    // levels 2..4 exact no-ops iff every lane's WL underflowed to 0
    const int trunc2 = __syncthreads_and(WL[2] == 0.f && WL[3] == 0.f && WL[4] == 0.f);
    const float WT1 = s_red[1], WT2 = s_red[2];

    // init: u0 = exp(init) * emission(t=0)
    float um[3], ui[3], ux = 0.f;
    {
        const float* ob = g_eobs + s_let[0];
        #pragma unroll
        for (int q = 0; q < 3; q++) {
            um[q] = g_einit[j0 + q]      * ob[j0 + q];
            ui[q] = g_einit[MM + j0 + q] * ob[MM + j0 + q];
        }
        if (l127) ux = g_einit[KK - 1] * ob[KK - 1];
        if (tid == 0) { ((float*)&s_bnd[0])[0] = 0.f; ((float*)&s_bnd[1])[0] = 0.f; }
        if (lane == 31 && wid < 3) ((float*)&s_bnd[0])[wid + 1] = um[2];
    }
    __syncthreads();

    int pacc = 0;
    float vm[3], vi[3], vx;

    if (trunc2) {
        stepfn<true, 0, 2>(um, ui, ux, vm, vi, vx, w_, cfa, cfb, cma, cmb, cia, cib, etm, eti,
                           WL, Wexcl, WT1, WT2, kw1, kw2, kw3, s_T, s_bnd, j0, lane, wid, l127,
                           et_x, ci_xa, ci_xb, g_eobs + s_let[1], pacc);
        for (int t = 2; t < LL; t += 2) {
            stepfn<true, 1, 2>(vm, vi, vx, um, ui, ux, w_, cfa, cfb, cma, cmb, cia, cib, etm, eti,
                               WL, Wexcl, WT1, WT2, kw1, kw2, kw3, s_T, s_bnd, j0, lane, wid, l127,
                               et_x, ci_xa, ci_xb, g_eobs + s_let[t], pacc);
            stepfn<false, 0, 2>(um, ui, ux, vm, vi, vx, w_, cfa, cfb, cma, cmb, cia, cib, etm, eti,
                                WL, Wexcl, WT1, WT2, kw1, kw2, kw3, s_T, s_bnd, j0, lane, wid, l127,
                                et_x, ci_xa, ci_xb, g_eobs + s_let[t + 1], pacc);
        }
    } else {
        stepfn<true, 0, 5>(um, ui, ux, vm, vi, vx, w_, cfa, cfb, cma, cmb, cia, cib, etm, eti,
                           WL, Wexcl, WT1, WT2, kw1, kw2, kw3, s_T, s_bnd, j0, lane, wid, l127,
                           et_x, ci_xa, ci_xb, g_eobs + s_let[1], pacc);
        for (int t = 2; t < LL; t += 2) {
            stepfn<true, 1, 5>(vm, vi, vx, um, ui, ux, w_, cfa, cfb, cma, cmb, cia, cib, etm, eti,
                               WL, Wexcl, WT1, WT2, kw1, kw2, kw3, s_T, s_bnd, j0, lane, wid, l127,
                               et_x, ci_xa, ci_xb, g_eobs + s_let[t], pacc);
            stepfn<false, 0, 5>(um, ui, ux, vm, vi, vx, w_, cfa, cfb, cma, cmb, cia, cib, etm, eti,
                                WL, Wexcl, WT1, WT2, kw1, kw2, kw3, s_T, s_bnd, j0, lane, wid, l127,
                                et_x, ci_xa, ci_xb, g_eobs + s_let[t + 1], pacc);
        }
    }

    // final: log(sum u) + 2^pacc correction
    float ps = ((vm[0] + vm[1]) + (vm[2] + vx)) + ((vi[0] + vi[1]) + vi[2]);
    #pragma unroll
    for (int o = 16; o; o >>= 1) ps += __shfl_xor_sync(0xffffffffu, ps, o);
    __syncthreads();                 // retire s_red (W totals) before reuse
    if (lane == 0) s_red[wid] = ps;
    __syncthreads();
    if (tid == 0) {
        float Zt = (s_red[0] + s_red[1]) + (s_red[2] + s_red[3]);
        out[b] = lscale[0] * ((float)((double)pacc * 0.6931471805599453) + __logf(Zt));
    }
}

extern "C" void kernel_launch(void* const* d_in, const int* in_sizes, int n_in,
                              void* d_out, int out_size)
{
    const float* pre  = (const float*)d_in[0];
    const float* iseq = (const float*)d_in[1];
    const float* ins  = (const float*)d_in[2];
    const float* del  = (const float*)d_in[3];
    const float* seq  = (const float*)d_in[4];
    const float* ls   = (const float*)d_in[5];
    float* out = (float*)d_out;

    prep_fused<<<3, 512>>>(pre, iseq, ins, del);
    hmm_forward<<<BB, 128>>>(seq, ls, out);
}

// round 17
// speedup vs baseline: 1.1037x; 1.1037x over previous
#include <cuda_runtime.h>
#include <math.h>

#define KK 769
#define MM 384
#define BB 64
#define LL 256
#define AA 21
#define ESTR 772
#define NEGV (-1.0e32f)

__device__ __align__(16) float g_eobs[(AA + 1) * ESTR];
__device__ float g_cm[KK];
__device__ float g_ci[KK];
__device__ float g_cf[KK];
__device__ float g_et[KK];
__device__ float g_w[MM];
__device__ float g_einit[KK];

// ---------------- fused prep: CTA0 = transition constants, CTA1-2 = emission table ----------------
__global__ __launch_bounds__(512) void prep_fused(
    const float* __restrict__ pre,  const float* __restrict__ iseq,
    const float* __restrict__ ins,  const float* __restrict__ del)
{
    const int tid = threadIdx.x, lane = tid & 31, wid = tid >> 5;

    if (blockIdx.x > 0) {
        // ---------- emission table: one state per thread ----------
        const int k = (blockIdx.x - 1) * 512 + tid;
        if (k >= KK) return;
        const float* row = (k < MM) ? (pre + k * AA) : (iseq + (k - MM) * AA);
        float mx = -INFINITY;
        #pragma unroll
        for (int a = 0; a < AA; a++) mx = fmaxf(mx, row[a]);
        float sm = 0.f;
        #pragma unroll
        for (int a = 0; a < AA; a++) sm += __expf(row[a] - mx);
        float l = mx + __logf(sm);
        float sm2 = 0.f;
        #pragma unroll
        for (int a = 0; a < AA; a++) sm2 += __expf(row[a] - l);
        float nrm = l + __logf(sm2);
        #pragma unroll
        for (int a = 0; a < AA; a++) g_eobs[a * ESTR + k] = __expf(row[a] - nrm);
        g_eobs[AA * ESTR + k] = 1.0f;
        return;
    }

    // ---------- CTA 0: transition constants + init ----------
    __shared__ float lre[(MM + 1) * 6], lue[(MM + 1) * 6];
    __shared__ float sC[MM + 2], sW2[MM + 1], sQt[MM + 1], sG[MM + 1];
    __shared__ float WT[16], ST[16], FIN[16], red[16];
    __shared__ float sInit[KK];

    for (int idx = tid; idx < MM * 3; idx += 512) {
        float x0 = ins[idx * 2], x1 = ins[idx * 2 + 1];
        float mx = fmaxf(x0, x1);
        float l = mx + __logf(__expf(x0 - mx) + __expf(x1 - mx));
        lre[idx * 2] = x0 - l; lre[idx * 2 + 1] = x1 - l;
        x0 = del[idx * 2]; x1 = del[idx * 2 + 1];
        mx = fmaxf(x0, x1);
        l = mx + __logf(__expf(x0 - mx) + __expf(x1 - mx));
        lue[idx * 2] = x0 - l; lue[idx * 2 + 1] = x1 - l;
    }
    if (tid < 3) {
        lre[(MM * 3 + tid) * 2 + 0] = NEGV; lre[(MM * 3 + tid) * 2 + 1] = 0.f;
        lue[(MM * 3 + tid) * 2 + 0] = 0.f;  lue[(MM * 3 + tid) * 2 + 1] = NEGV;
    }
    __syncthreads();

    { // C (exclusive cumsum of d2), w2, Qt
        float d2 = 0.f;
        if (tid < MM) d2 = lre[(tid * 3 + 2) * 2 + 0] + lue[(tid * 3 + 2) * 2 + 1];
        float inc = d2;
        #pragma unroll
        for (int o = 1; o < 32; o <<= 1) {
            float t = __shfl_up_sync(0xffffffffu, inc, o);
            if (lane >= o) inc += t;
        }
        if (lane == 31) WT[wid] = inc;
        __syncthreads();
        float off = 0.f;
        for (int j = 0; j < wid; j++) off += WT[j];
        if (tid < MM) { sC[tid + 1] = inc + off; sW2[tid] = __expf(d2); }
        if (tid == 0) { sC[0] = 0.f; sC[MM + 1] = 0.f; sW2[MM] = 0.f; }
        if (tid <= MM) {
            float q = __expf(lre[(tid * 3 + 2) * 2 + 1]);
            if (tid < MM) q += __expf(lre[(tid * 3 + 2) * 2 + 0] + lue[(tid * 3 + 2) * 2 + 0]);
            sQt[tid] = q;
        }
        __syncthreads();
    }
    { // G via reverse affine scan
        float A = 1.f, Bv = 0.f;
        if (tid < MM) { A = sW2[MM - tid]; Bv = sQt[MM - tid]; }
        #pragma unroll
        for (int o = 1; o < 32; o <<= 1) {
            float Wp = __shfl_up_sync(0xffffffffu, A, o);
            float Sp = __shfl_up_sync(0xffffffffu, Bv, o);
            if (lane >= o) { Bv = fmaf(A, Sp, Bv); A *= Wp; }
        }
        if (lane == 31 && wid < 12) { WT[wid] = A; ST[wid] = Bv; }
        __syncthreads();
        if (wid == 0) {
            float Wt = (lane < 12) ? WT[lane] : 1.f;
            float St = (lane < 12) ? ST[lane] : 0.f;
            #pragma unroll
            for (int o = 1; o < 16; o <<= 1) {
                float Wp = __shfl_up_sync(0xffffffffu, Wt, o);
                float Sp = __shfl_up_sync(0xffffffffu, St, o);
                if (lane >= o) { St = fmaf(Wt, Sp, St); Wt *= Wp; }
            }
            float e = __shfl_up_sync(0xffffffffu, St, 1);
            if (lane == 0) e = 0.f;
            if (lane < 12) FIN[lane] = e;
        }
        __syncthreads();
        if (tid < MM) sG[MM - 1 - tid] = fmaf(A, FIN[wid], Bv);
        if (tid == 0) sG[MM] = 0.f;
        __syncthreads();
    }
    for (int k = tid; k < KK; k += 512) {
        const int m = (k < MM) ? k : k - MM;
        const int g = (k < MM) ? 0 : 1;
        const int s = m + 1 - g;
        float src_stay  = lre[(s * 3 + g) * 2 + 0];
        float src_ins   = lre[(s * 3 + g) * 2 + 1];
        float src_match = lue[(s * 3 + g) * 2 + 0];
        float src_del   = lue[(s * 3 + g) * 2 + 1];
        float dmatch = src_stay + src_match, dins = src_ins, cflog = src_stay + src_del;
        float rowsum = __expf(dins) + ((s < MM) ? __expf(dmatch) : 0.f) + __expf(cflog) * sG[s];
        float lse = __logf(rowsum);
        g_cm[k] = __expf(dmatch - lse);
        g_ci[k] = __expf(dins - lse);
        g_cf[k] = __expf(cflog - lse);
        float tterm = (g == 1) ? lre[(m * 3 + 2) * 2 + 1]
                               : (lre[(m * 3 + 2) * 2 + 0] + lue[(m * 3 + 2) * 2 + 0]);
        g_et[k] = __expf(tterm);
        float initv;
        if (m == 0) initv = (g == 1) ? lre[1] : (lre[0] + lue[0]);
        else        initv = lre[0] + lue[1] - sC[1] + sC[m] + tterm;
        sInit[k] = initv;
    }
    if (tid < MM) g_w[tid] = sW2[tid];
    __syncthreads();
    { // normalized exp(init)
        float mloc = -INFINITY;
        for (int k = tid; k < KK; k += 512) mloc = fmaxf(mloc, sInit[k]);
        #pragma unroll
        for (int o = 16; o; o >>= 1) mloc = fmaxf(mloc, __shfl_xor_sync(0xffffffffu, mloc, o));
        if (lane == 0) red[wid] = mloc;
        __syncthreads();
        float mxI = red[0];
        #pragma unroll
        for (int j = 1; j < 16; j++) mxI = fmaxf(mxI, red[j]);
        __syncthreads();
        float s0 = 0.f;
        for (int k = tid; k < KK; k += 512) s0 += __expf(sInit[k] - mxI);
        #pragma unroll
        for (int o = 16; o; o >>= 1) s0 += __shfl_xor_sync(0xffffffffu, s0, o);
        if (lane == 0) red[wid] = s0;
        __syncthreads();
        float Z = 0.f;
        for (int j = 0; j < 16; j++) Z += red[j];
        float lz = mxI + __logf(Z);
        for (int k = tid; k < KK; k += 512) g_einit[k] = __expf(sInit[k] - lz);
    }
}

// ---------------- one forward step: constant-W scan (NLEV levels), ONE barrier ----------------
template <bool RESC, int P, int NLEV>
__device__ __forceinline__ void stepfn(
    const float (&um)[3], const float (&ui)[3], float uxin,
    float (&vm)[3], float (&vi)[3], float& vx,
    const float (&w_)[3], const float (&cfa)[3], const float (&cfb)[3],
    const float (&cma)[3], const float (&cmb)[3],
    const float (&cia)[3], const float (&cib)[3],
    const float (&etm)[3], const float (&eti)[3],
    const float (&WL)[5], float Wexcl, float WT1, float WT2,
    float kw1, float kw2, float kw3,
    float2 (*s_T)[4], float4* s_bnd,
    int j0, int lane, int wid, bool l127,
    float et_x, float ci_xa, float ci_xb,
    const float* __restrict__ ob, int& pacc)
{
    float em[3], ei[3];
    #pragma unroll
    for (int q = 0; q < 3; q++) { em[q] = ob[j0 + q]; ei[q] = ob[MM + j0 + q]; }
    float e_x = l127 ? ob[KK - 1] : 0.f;

    float ubm1 = __shfl_up_sync(0xffffffffu, um[2], 1);
    float ub_s = lane ? ubm1 : 0.f;

    float Sr[3];
    Sr[0] = fmaf(ub_s, cfb[0], ui[0] * cfa[0]);
    Sr[1] = fmaf(um[0], cfb[1], ui[1] * cfa[1]);
    Sr[2] = fmaf(um[1], cfb[2], ui[2] * cfa[2]);
    float Sv = Sr[0];
    Sv = fmaf(w_[1], Sv, Sr[1]);
    Sv = fmaf(w_[2], Sv, Sr[2]);

    // S-only inclusive affine scan; levels >= NLEV are exact no-ops for every
    // PARTICIPATING lane (lane >= o implies WL[k] == 0; lane < o never updates)
    #pragma unroll
    for (int k = 0; k < NLEV; k++) {
        const int o = 1 << k;
        float Sp = __shfl_up_sync(0xffffffffu, Sv, o);
        if (lane >= o) Sv = fmaf(WL[k], Sp, Sv);
    }

    float zs = 0.f;
    if (RESC) {
        zs = ((um[0] + um[1]) + (um[2] + uxin)) + ((ui[0] + ui[1]) + ui[2]);
        #pragma unroll
        for (int o = 16; o; o >>= 1) zs += __shfl_xor_sync(0xffffffffu, zs, o);
    }
    float Sp1 = __shfl_up_sync(0xffffffffu, Sv, 1);   // pre-barrier
    if (lane == 31) s_T[P][wid] = make_float2(Sv, zs);
    __syncthreads();

    float2 T0 = s_T[P][0], T1 = s_T[P][1], T2 = s_T[P][2];
    float rz = 1.f;
    if (RESC) {
        float2 T3 = s_T[P][3];
        float Tz = (T0.y + T1.y) + (T2.y + T3.y);
        unsigned ze = (__float_as_uint(Tz) >> 23) & 255u;
        pacc += (int)ze - 127;
        rz = __uint_as_float((254u - ze) << 23);
    }
    float4 bv = s_bnd[P];
    float bc1 = bv.y * kw1, bc2 = bv.z * kw2, bc3 = bv.w * kw3;
    float Fin;
    if (NLEV == 2) {
        // warp-total W's (96 w-factors) are exact zeros in the truncated regime
        Fin = (wid == 0) ? 0.f
            : (wid == 1) ? (T0.x + bc1)
            : (wid == 2) ? (T1.x + bc2)
                         : (T2.x + bc3);
    } else {
        Fin = 0.f;
        if (wid > 0) Fin = T0.x + bc1;
        if (wid > 1) Fin = fmaf(WT1, Fin, T1.x) + bc2;
        if (wid > 2) Fin = fmaf(WT2, Fin, T2.x) + bc3;
    }

    float Fexp = lane ? fmaf(Wexcl, Fin, Sp1) : Fin;
    float bc_own = (wid == 1) ? bc1 : ((wid == 2) ? bc2 : ((wid == 3) ? bc3 : 0.f));
    float ubw    = (wid == 1) ? bv.y : ((wid == 2) ? bv.z : ((wid == 3) ? bv.w : 0.f));
    float F0  = lane ? Fexp : (Fexp - bc_own);
    float ub0 = lane ? ubm1 : ubw;

    float prm = fmaf(ub0, cmb[0], fmaf(ui[0], cma[0], etm[0] * F0));
    float pri = fmaf(ub0, cib[0], fmaf(ui[0], cia[0], eti[0] * F0));
    vm[0] = RESC ? prm * em[0] * rz : prm * em[0];
    vi[0] = RESC ? pri * ei[0] * rz : pri * ei[0];
    float F = fmaf(w_[0], Fexp, Sr[0]);
    prm = fmaf(um[0], cmb[1], fmaf(ui[1], cma[1], etm[1] * F));
    pri = fmaf(um[0], cib[1], fmaf(ui[1], cia[1], eti[1] * F));
    vm[1] = RESC ? prm * em[1] * rz : prm * em[1];
    vi[1] = RESC ? pri * ei[1] * rz : pri * ei[1];
    F = fmaf(w_[1], F, Sr[1]);
    prm = fmaf(um[1], cmb[2], fmaf(ui[2], cma[2], etm[2] * F));
    pri = fmaf(um[1], cib[2], fmaf(ui[2], cia[2], eti[2] * F));
    vm[2] = RESC ? prm * em[2] * rz : prm * em[2];
    vi[2] = RESC ? pri * ei[2] * rz : pri * ei[2];
    vx = 0.f;
    if (l127) {
        F = fmaf(w_[2], F, Sr[2]);
        float prx = fmaf(et_x, F, fmaf(um[2], ci_xb, uxin * ci_xa));
        vx = RESC ? prx * e_x * rz : prx * e_x;
    }
    if (lane == 31 && wid < 3)
        ((float*)&s_bnd[P ^ 1])[wid + 1] = vm[2];
}

// ---------------- forward recursion: 4 warps, alpha in registers, 1 bar/step ----------------
__global__ void __launch_bounds__(128) hmm_forward(const float* __restrict__ seq,
                                                   const float* __restrict__ lscale,
                                                   float* __restrict__ out)
{
    __shared__ float2 s_T[2][4];
    __shared__ float4 s_bnd[2];
    __shared__ float  s_red[4];
    __shared__ int    s_let[LL];

    const int b = blockIdx.x, tid = threadIdx.x, lane = tid & 31, wid = tid >> 5;
    const int j0 = tid * 3;
    const bool l127 = (tid == 127);

    for (int l = tid; l < LL; l += 128) {
        const float* row = seq + ((size_t)b * LL + l) * AA;
        int let = AA;
        #pragma unroll
        for (int a = 0; a < AA; a++)
            if (row[a] > 0.5f) let = a;
        s_let[l] = let * ESTR;
    }

    float w_[3], cfa[3], cfb[3], cma[3], cmb[3], cia[3], cib[3], etm[3], eti[3];
    #pragma unroll
    for (int q = 0; q < 3; q++) {
        const int j = j0 + q;
        w_[q]  = g_w[j];
        cfa[q] = g_cf[MM + j];  cfb[q] = j ? g_cf[j - 1] : 0.f;
        cma[q] = g_cm[MM + j];  cmb[q] = j ? g_cm[j - 1] : 0.f;
        cia[q] = g_ci[MM + j];  cib[q] = j ? g_ci[j - 1] : 0.f;
        etm[q] = g_et[j];       eti[q] = g_et[MM + j];
    }
    const float kw1 = __fdividef(g_cf[95],  g_w[96]);
    const float kw2 = __fdividef(g_cf[191], g_w[192]);
    const float kw3 = __fdividef(g_cf[287], g_w[288]);
    float et_x = 0.f, ci_xa = 0.f, ci_xb = 0.f;
    if (l127) { et_x = g_et[KK - 1]; ci_xa = g_ci[KK - 1]; ci_xb = g_ci[MM - 1]; }

    // constant-W scan multipliers (one dummy W-only scan)
    float WL[5], Wfin;
    {
        float Wv = w_[0] * w_[1] * w_[2];
        #pragma unroll
        for (int k = 0; k < 5; k++) {
            const int o = 1 << k;
            WL[k] = Wv;
            float Wp = __shfl_up_sync(0xffffffffu, Wv, o);
            if (lane >= o) Wv *= Wp;
        }
        Wfin = Wv;
    }
    const float Wexcl = __shfl_up_sync(0xffffffffu, Wfin, 1);
    if (lane == 31) s_red[wid] = Wfin;

    // CORRECTED truncation gate: level k is an exact no-op for lane L iff
    // (lane < o: never updates) OR (WL[k] == 0). Previous gate wrongly demanded
    // WL[k]==0 on non-participating lanes too, so the fast path never ran.
    bool zk = true;
    #pragma unroll
    for (int k = 2; k < 5; k++)
        if (lane >= (1 << k) && WL[k] != 0.f) zk = false;
    const int trunc2 = __syncthreads_and(zk);
    const float WT1 = s_red[1], WT2 = s_red[2];

    // init: u0 = exp(init) * emission(t=0)
    float um[3], ui[3], ux = 0.f;
    {
        const float* ob = g_eobs + s_let[0];
        #pragma unroll
        for (int q = 0; q < 3; q++) {
            um[q] = g_einit[j0 + q]      * ob[j0 + q];
            ui[q] = g_einit[MM + j0 + q] * ob[MM + j0 + q];
        }
        if (l127) ux = g_einit[KK - 1] * ob[KK - 1];
        if (tid == 0) { ((float*)&s_bnd[0])[0] = 0.f; ((float*)&s_bnd[1])[0] = 0.f; }
        if (lane == 31 && wid < 3) ((float*)&s_bnd[0])[wid + 1] = um[2];
    }
    __syncthreads();

    int pacc = 0;
    float vm[3], vi[3], vx;

    if (trunc2) {
        stepfn<true, 0, 2>(um, ui, ux, vm, vi, vx, w_, cfa, cfb, cma, cmb, cia, cib, etm, eti,
                           WL, Wexcl, WT1, WT2, kw1, kw2, kw3, s_T, s_bnd, j0, lane, wid, l127,
                           et_x, ci_xa, ci_xb, g_eobs + s_let[1], pacc);
        for (int t = 2; t < LL; t += 2) {
            stepfn<true, 1, 2>(vm, vi, vx, um, ui, ux, w_, cfa, cfb, cma, cmb, cia, cib, etm, eti,
                               WL, Wexcl, WT1, WT2, kw1, kw2, kw3, s_T, s_bnd, j0, lane, wid, l127,
                               et_x, ci_xa, ci_xb, g_eobs + s_let[t], pacc);
            stepfn<false, 0, 2>(um, ui, ux, vm, vi, vx, w_, cfa, cfb, cma, cmb, cia, cib, etm, eti,
                                WL, Wexcl, WT1, WT2, kw1, kw2, kw3, s_T, s_bnd, j0, lane, wid, l127,
                                et_x, ci_xa, ci_xb, g_eobs + s_let[t + 1], pacc);
        }
    } else {
        stepfn<true, 0, 5>(um, ui, ux, vm, vi, vx, w_, cfa, cfb, cma, cmb, cia, cib, etm, eti,
                           WL, Wexcl, WT1, WT2, kw1, kw2, kw3, s_T, s_bnd, j0, lane, wid, l127,
                           et_x, ci_xa, ci_xb, g_eobs + s_let[1], pacc);
        for (int t = 2; t < LL; t += 2) {
            stepfn<true, 1, 5>(vm, vi, vx, um, ui, ux, w_, cfa, cfb, cma, cmb, cia, cib, etm, eti,
                               WL, Wexcl, WT1, WT2, kw1, kw2, kw3, s_T, s_bnd, j0, lane, wid, l127,
                               et_x, ci_xa, ci_xb, g_eobs + s_let[t], pacc);
            stepfn<false, 0, 5>(um, ui, ux, vm, vi, vx, w_, cfa, cfb, cma, cmb, cia, cib, etm, eti,
                                WL, Wexcl, WT1, WT2, kw1, kw2, kw3, s_T, s_bnd, j0, lane, wid, l127,
                                et_x, ci_xa, ci_xb, g_eobs + s_let[t + 1], pacc);
        }
    }

    // final: log(sum u) + 2^pacc correction
    float ps = ((vm[0] + vm[1]) + (vm[2] + vx)) + ((vi[0] + vi[1]) + vi[2]);
    #pragma unroll
    for (int o = 16; o; o >>= 1) ps += __shfl_xor_sync(0xffffffffu, ps, o);
    __syncthreads();                 // retire s_red (W totals) before reuse
    if (lane == 0) s_red[wid] = ps;
    __syncthreads();
    if (tid == 0) {
        float Zt = (s_red[0] + s_red[1]) + (s_red[2] + s_red[3]);
        out[b] = lscale[0] * ((float)((double)pacc * 0.6931471805599453) + __logf(Zt));
    }
}

extern "C" void kernel_launch(void* const* d_in, const int* in_sizes, int n_in,
                              void* d_out, int out_size)
{
    const float* pre  = (const float*)d_in[0];
    const float* iseq = (const float*)d_in[1];
    const float* ins  = (const float*)d_in[2];
    const float* del  = (const float*)d_in[3];
    const float* seq  = (const float*)d_in[4];
    const float* ls   = (const float*)d_in[5];
    float* out = (float*)d_out;

    prep_fused<<<3, 512>>>(pre, iseq, ins, del);
    hmm_forward<<<BB, 128>>>(seq, ls, out);
}